// round 7
// baseline (speedup 1.0000x reference)
#include <cuda_runtime.h>

// fm: (1, 256, 256, 256) fp32 NHWC; rois: (2000, 5) int32 [b, x, y, w, h]; pool = 7.
#define FM_W 256
#define FM_C 256
#define POOLSZ 7
#define NCELL (POOLSZ * POOLSZ)

// 128-bit feature-map load with an L2 evict_last cache-hint policy (the bare
// .L2::evict_last modifier needs 256-bit loads; the createpolicy/cache_hint
// form works with .v4.f32 + 16B alignment).
__device__ __forceinline__ float4 ldg_evl(const float4* p, unsigned long long pol) {
    float4 v;
    asm("ld.global.nc.L2::cache_hint.v4.f32 {%0,%1,%2,%3}, [%4], %5;"
        : "=f"(v.x), "=f"(v.y), "=f"(v.z), "=f"(v.w) : "l"(p), "l"(pol));
    return v;
}

__global__ __launch_bounds__(256) void roi_pool_kernel(
    const float* __restrict__ fm,      // [H, W, C]
    const int* __restrict__ rois,      // [N, 5]
    float* __restrict__ out)           // [N, 7, 7, C]
{
    int roi = blockIdx.x;
    int tid = threadIdx.x;

    __shared__ int   sx0[POOLSZ], sx1[POOLSZ], sy0[POOLSZ], sy1[POOLSZ];
    __shared__ float sfx[POOLSZ], sfy[POOLSZ];
    // NOTE: int4/float4 element type guarantees the 16B alignment that the
    // LDS.128 broadcast reads below require (int[49][4] only guaranteed 4B —
    // that was the "misaligned address" crash in R4-R6).
    __shared__ int4   sIdx[NCELL];   // float4-unit base index of the 4 corner pixels
    __shared__ float4 sWt[NCELL];    // fused bilinear weights w00,w01,w10,w11

    // Phase 1: 14 threads compute the two axes' sample coordinates.
    if (tid < 2 * POOLSZ) {
        int  p   = (tid >= POOLSZ) ? tid - POOLSZ : tid;
        bool isx = tid < POOLSZ;
        int start = rois[roi * 5 + (isx ? 1 : 2)];
        int len   = rois[roi * 5 + (isx ? 3 : 4)];
        float lf = (float)len;
        float f = ((float)p + 0.5f) * (lf / (float)POOLSZ) - 0.5f;
        f = fminf(fmaxf(f, 0.0f), lf - 1.0f);
        int i0 = (int)floorf(f);
        int i1 = min(i0 + 1, len - 1);
        float fr = f - (float)i0;
        if (isx) { sx0[p] = start + i0; sx1[p] = start + i1; sfx[p] = fr; }
        else     { sy0[p] = start + i0; sy1[p] = start + i1; sfy[p] = fr; }
    }
    __syncthreads();

    // Phase 2: 49 threads fuse per-cell corner indices + weights.
    if (tid < NCELL) {
        int py = tid / POOLSZ;
        int px = tid - py * POOLSZ;
        int y0 = sy0[py], y1 = sy1[py];
        int x0 = sx0[px], x1 = sx1[px];
        float fy = sfy[py], fx = sfx[px];
        float ofx = 1.0f - fx, ofy = 1.0f - fy;
        int4 idx;
        idx.x = (y0 * FM_W + x0) * (FM_C / 4);
        idx.y = (y0 * FM_W + x1) * (FM_C / 4);
        idx.z = (y1 * FM_W + x0) * (FM_C / 4);
        idx.w = (y1 * FM_W + x1) * (FM_C / 4);
        sIdx[tid] = idx;
        float4 w;
        w.x = ofx * ofy;
        w.y = fx  * ofy;
        w.z = ofx * fy;
        w.w = fx  * fy;
        sWt[tid] = w;
    }
    __syncthreads();

    // Evict-last policy for the feature map (created once per thread).
    unsigned long long pol;
    asm("createpolicy.fractional.L2::evict_last.b64 %0, 1.0;" : "=l"(pol));

    int c  = tid & 63;        // channel float4 index 0..63
    int ty = tid >> 6;        // cell-group 0..3

    const float4* f4 = (const float4*)fm;
    float4* o4 = (float4*)out + (size_t)roi * NCELL * (FM_C / 4);

    #pragma unroll 4
    for (int cell = ty; cell < NCELL; cell += 4) {
        int4   idx = sIdx[cell];    // broadcast LDS.128
        float4 w   = sWt[cell];     // broadcast LDS.128

        const float4 g00 = ldg_evl(f4 + idx.x + c, pol);
        const float4 g01 = ldg_evl(f4 + idx.y + c, pol);
        const float4 g10 = ldg_evl(f4 + idx.z + c, pol);
        const float4 g11 = ldg_evl(f4 + idx.w + c, pol);

        float4 r;
        r.x = g00.x * w.x + g01.x * w.y + g10.x * w.z + g11.x * w.w;
        r.y = g00.y * w.x + g01.y * w.y + g10.y * w.z + g11.y * w.w;
        r.z = g00.z * w.x + g01.z * w.y + g10.z * w.z + g11.z * w.w;
        r.w = g00.w * w.x + g01.w * w.y + g10.w * w.z + g11.w * w.w;

        // Streaming store: output is written once, never read — evict first.
        __stcs(&o4[cell * (FM_C / 4) + c], r);
    }
}

extern "C" void kernel_launch(void* const* d_in, const int* in_sizes, int n_in,
                              void* d_out, int out_size)
{
    const float* fm  = (const float*)d_in[0];
    const int* rois  = (const int*)d_in[1];
    float* out       = (float*)d_out;

    int n_rois = in_sizes[1] / 5;

    roi_pool_kernel<<<n_rois, 256>>>(fm, rois, out);
}